// round 10
// baseline (speedup 1.0000x reference)
#include <cuda_runtime.h>
#include <stdint.h>

#define B 8
#define H 1024
#define W 1024
#define NPIX (H * W)
#define SAL_ELEMS (B * 3 * NPIX)
#define NPAIRS (H * (W - 1))
#define MAXAB 64      // g_aband stride (>= NAB)
#define NAB 52        // merged band count

// ---------------- scratch ----------------
__device__ float g_aband[B * MAXAB * W];      // [b][atomic band][col], 2 MB
__device__ unsigned g_d2part[B * NAB];
__device__ int g_tier[B];
__device__ float g_segmean[B * 3 * 256];

// tier x map geometry: n = BASE[t]+(m-1)*INCR[t]; gr=round(sqrt n); gc=ceil(n/gr)
__constant__ int c_gr[3][3] = { {4, 5, 6}, {8, 9, 10}, {11, 12, 13} };
__constant__ int c_gc[3][3] = { {5, 6, 7}, {9, 9, 10}, {12, 13, 14} };
__constant__ int c_base[3] = { 30, 80, 150 };
__constant__ int c_incr[3] = { 10, 15, 25 };

// Merged row-band boundaries: union over gr in {4,5,6,8,9,10,11,12,13} of
// { ceil(1024*k/gr) : k=0..gr-1 }, sorted, + sentinel 1024. 52 bands.
__constant__ int c_bs[NAB + 1] = {
    0, 79, 86, 94, 103, 114, 128, 158, 171, 187, 205, 228, 237, 256, 280,
    308, 316, 342, 373, 384, 394, 410, 427, 456, 466, 473, 512, 552, 559,
    569, 598, 615, 631, 640, 652, 683, 709, 717, 745, 768, 788, 797, 820,
    838, 854, 867, 896, 911, 922, 931, 939, 946, 1024
};

// ---------------- K1: band-aligned gray + complexity + band sums ----------------
// Block = (atomic band, batch). Each block owns rows [c_bs[ab], c_bs[ab+1]):
// accumulates privately, ONE plain float4 store. No atomics, no zero pass.
__global__ __launch_bounds__(256) void k_band(const float* __restrict__ img) {
    __shared__ unsigned s_w[8];

    int ab = blockIdx.x;          // 0..51
    int b = blockIdx.y;
    int r0 = c_bs[ab], r1 = c_bs[ab + 1];
    int t = threadIdx.x;
    int col = t << 2;
    int lane = t & 31;
    unsigned mask = 0xFFFFFFFFu;

    float4 acc = make_float4(0.f, 0.f, 0.f, 0.f);
    unsigned d2 = 0;
    const float* base = img + (size_t)b * 3 * NPIX + col;

#pragma unroll 2
    for (int r = r0; r < r1; r++) {
        const float* p = base + (size_t)r * W;
        float4 r4 = __ldcs((const float4*)p);
        float4 g4 = __ldcs((const float4*)(p + NPIX));
        float4 b4 = __ldcs((const float4*)(p + 2 * NPIX));

        float gy0 = 0.299f * r4.x + 0.587f * g4.x + 0.114f * b4.x;
        float gy1 = 0.299f * r4.y + 0.587f * g4.y + 0.114f * b4.y;
        float gy2 = 0.299f * r4.z + 0.587f * g4.z + 0.114f * b4.z;
        float gy3 = 0.299f * r4.w + 0.587f * g4.w + 0.114f * b4.w;

        acc.x += (r4.x + g4.x + b4.x) * (1.0f / 3.0f);
        acc.y += (r4.y + g4.y + b4.y) * (1.0f / 3.0f);
        acc.z += (r4.z + g4.z + b4.z) * (1.0f / 3.0f);
        acc.w += (r4.w + g4.w + b4.w) * (1.0f / 3.0f);

        float gnext = __shfl_down_sync(mask, gy0, 1);
        if (lane == 31 && col + 4 < W) {
            const float* q = p + 4;
            gnext = 0.299f * q[0] + 0.587f * q[NPIX] + 0.114f * q[2 * NPIX];
        }

        int i0 = min(max((int)(gy0 * 255.0f), 0), 255);
        int i1 = min(max((int)(gy1 * 255.0f), 0), 255);
        int i2 = min(max((int)(gy2 * 255.0f), 0), 255);
        int i3 = min(max((int)(gy3 * 255.0f), 0), 255);

        int d;
        d = i0 - i1; d2 += (unsigned)(d * d);
        d = i1 - i2; d2 += (unsigned)(d * d);
        d = i2 - i3; d2 += (unsigned)(d * d);
        if (col + 3 < W - 1) {
            int i4 = min(max((int)(gnext * 255.0f), 0), 255);
            d = i3 - i4; d2 += (unsigned)(d * d);
        }
    }

    *(float4*)(g_aband + ((size_t)b * MAXAB + ab) * W + col) = acc;

    // block-reduce d2 -> one partial per (b, band)
    d2 = __reduce_add_sync(mask, d2);
    if (lane == 0) s_w[t >> 5] = d2;
    __syncthreads();
    if (t == 0) {
        unsigned tot = 0;
#pragma unroll
        for (int i = 0; i < 8; i++) tot += s_w[i];
        g_d2part[b * NAB + ab] = tot;
    }
}

// ---------------- K2: segment means (tier computed inline) ----------------
__global__ __launch_bounds__(32) void k_segmean(float* __restrict__ out, int write_tail) {
    int b = blockIdx.z, m = blockIdx.y, seg = blockIdx.x;
    int lane = threadIdx.x;
    unsigned mask = 0xFFFFFFFFu;

    // inline complexity reduce (52 u32 partials, L2-hot) -> tier, all lanes
    unsigned long long s64 = (unsigned long long)g_d2part[b * NAB + lane];
    if (lane + 32 < NAB) s64 += (unsigned long long)g_d2part[b * NAB + 32 + lane];
#pragma unroll
    for (int o = 16; o > 0; o >>= 1) s64 += __shfl_xor_sync(mask, s64, o);
    float comp = (float)s64 / (float)NPAIRS;
    int tier = (comp < 50.0f) ? 0 : ((comp < 150.0f) ? 1 : 2);

    if (m == 0 && seg == 0 && lane == 0) {
        g_tier[b] = tier;
        if (write_tail) {
            out[SAL_ELEMS + b] = comp;
#pragma unroll
            for (int mm = 0; mm < 3; mm++)
                out[SAL_ELEMS + B + b * 3 + mm] = (float)(c_base[tier] + (mm - 1) * c_incr[tier]);
        }
    }

    int gr = c_gr[tier][m], gc = c_gc[tier][m];
    if (seg >= gr * gc) return;
    int r = seg / gc, c = seg - r * gc;
    int r0 = (r * H + gr - 1) / gr;
    int r1 = ((r + 1) * H + gr - 1) / gr; if (r1 > H) r1 = H;
    int c0 = (c * W + gc - 1) / gc;
    int c1 = ((c + 1) * W + gc - 1) / gc; if (c1 > W) c1 = W;

    float s = 0.0f;
    for (int ab = 0; ab < NAB; ab++) {
        int bs = c_bs[ab];
        if (bs >= r0 && bs < r1) {
            const float* p = g_aband + ((size_t)b * MAXAB + ab) * W;
            for (int col = c0 + lane; col < c1; col += 32) s += p[col];
        }
    }
#pragma unroll
    for (int o = 16; o > 0; o >>= 1) s += __shfl_down_sync(mask, s, o);
    if (lane == 0) {
        int cnt = (r1 - r0) * (c1 - c0);
        g_segmean[((size_t)b * 3 + m) * 256 + seg] = s / (float)cnt;
    }
}

// ---------------- K3: fill saliency, 8 floats/thread, branch-free ----------------
// Column bands are >= 73 px wide, so 8 consecutive pixels cross at most one
// boundary: two loads + per-element select, no divergence.
__global__ __launch_bounds__(256) void k_fill(float* __restrict__ out) {
    int idx = blockIdx.x * 256 + threadIdx.x;   // 8-float group index
    int bm = idx >> 17;                          // 131072 groups per map
    int within = idx & 131071;
    int row = within >> 7;                       // 128 groups per row
    int col = (within & 127) << 3;

    int b = bm / 3;
    int m = bm - b * 3;
    int tier = g_tier[b];
    int gr = c_gr[tier][m], gc = c_gc[tier][m];
    const float* sm = g_segmean + (size_t)bm * 256;

    int rb = (row * gr) >> 10;
    int basei = rb * gc;

    int cb0 = (col * gc) >> 10;
    int cb7 = ((col + 7) * gc) >> 10;
    float a = sm[basei + cb0];
    float bv = sm[basei + cb7];
    int bpos = (cb7 * 1024 + gc - 1) / gc;      // first column in band cb7

    float4 q0, q1;
    q0.x = (col + 0 >= bpos) ? bv : a;
    q0.y = (col + 1 >= bpos) ? bv : a;
    q0.z = (col + 2 >= bpos) ? bv : a;
    q0.w = (col + 3 >= bpos) ? bv : a;
    q1.x = (col + 4 >= bpos) ? bv : a;
    q1.y = (col + 5 >= bpos) ? bv : a;
    q1.z = (col + 6 >= bpos) ? bv : a;
    q1.w = (col + 7 >= bpos) ? bv : a;

    float4* dst = (float4*)(out + (size_t)bm * NPIX + (size_t)row * W + col);
    __stcs(dst + 0, q0);
    __stcs(dst + 1, q1);
}

// ---------------- launch ----------------
extern "C" void kernel_launch(void* const* d_in, const int* in_sizes, int n_in,
                              void* d_out, int out_size) {
    const float* img = (const float*)d_in[0];
    float* out = (float*)d_out;
    int write_tail = (out_size >= SAL_ELEMS + B + B * 3) ? 1 : 0;

    dim3 gb(NAB, B);
    k_band<<<gb, 256>>>(img);
    dim3 gsm(182, 3, B);
    k_segmean<<<gsm, 32>>>(out, write_tail);
    k_fill<<<(SAL_ELEMS / 8) / 256, 256>>>(out);
}

// round 12
// speedup vs baseline: 1.5000x; 1.5000x over previous
#include <cuda_runtime.h>
#include <stdint.h>

#define B 8
#define H 1024
#define W 1024
#define NPIX (H * W)
#define SAL_ELEMS (B * 3 * NPIX)
#define NPAIRS (H * (W - 1))
#define MAXAB 64      // g_aband stride (>= NAB)
#define NAB 52        // merged band count

// ---------------- scratch ----------------
__device__ float g_aband[B * MAXAB * W];      // [b][atomic band][col], 2 MB
__device__ unsigned g_d2part[B * 64];
__device__ int g_tier[B];
__device__ float g_segmean[B * 3 * 256];

// tier x map geometry: n = BASE[t]+(m-1)*INCR[t]; gr=round(sqrt n); gc=ceil(n/gr)
__constant__ int c_gr[3][3] = { {4, 5, 6}, {8, 9, 10}, {11, 12, 13} };
__constant__ int c_gc[3][3] = { {5, 6, 7}, {9, 9, 10}, {12, 13, 14} };
__constant__ int c_base[3] = { 30, 80, 150 };
__constant__ int c_incr[3] = { 10, 15, 25 };

// Merged row-band boundaries: union over gr in {4,5,6,8,9,10,11,12,13} of
// { ceil(1024*k/gr) : k=0..gr-1 }, sorted, + sentinel 1024. 52 bands.
__constant__ int c_bs[NAB + 1] = {
    0, 79, 86, 94, 103, 114, 128, 158, 171, 187, 205, 228, 237, 256, 280,
    308, 316, 342, 373, 384, 394, 410, 427, 456, 466, 473, 512, 552, 559,
    569, 598, 615, 631, 640, 652, 683, 709, 717, 745, 768, 788, 797, 820,
    838, 854, 867, 896, 911, 922, 931, 939, 946, 1024
};

// ---------------- K0: zero atomic-band accumulators ----------------
__global__ __launch_bounds__(256) void k_zero() {
    int i = blockIdx.x * 256 + threadIdx.x;     // float4 index; 512*256 exact
    ((float4*)g_aband)[i] = make_float4(0.f, 0.f, 0.f, 0.f);
}

// ---------------- K1: fused gray + complexity + row-band sums ----------------
// Block = (b, 16-row chunk): 512 balanced blocks. Per-thread accumulator
// flushes to g_aband via atomicAdd only at merged band boundaries.
__global__ __launch_bounds__(256) void k_gray(const float* __restrict__ img) {
    __shared__ unsigned s_w[8];

    int chunk = blockIdx.x & 63;
    int b = blockIdx.x >> 6;
    int rc0 = chunk << 4;
    int t = threadIdx.x;
    int col = t << 2;
    int lane = t & 31;
    unsigned mask = 0xFFFFFFFFu;

    // locate atomic band containing rc0 (uniform walk over constant table)
    int ab = 0;
    while (c_bs[ab + 1] <= rc0) ab++;
    int next = c_bs[ab + 1];

    float4 acc = make_float4(0.f, 0.f, 0.f, 0.f);
    bool dirty = false;
    unsigned d2 = 0;
    float* abandb = g_aband + (size_t)b * MAXAB * W + col;
    const float* base = img + (size_t)b * 3 * NPIX + col;

#pragma unroll 4
    for (int rr = 0; rr < 16; rr++) {
        int r = rc0 + rr;
        const float* p = base + (size_t)r * W;
        float4 r4 = __ldcs((const float4*)p);
        float4 g4 = __ldcs((const float4*)(p + NPIX));
        float4 b4 = __ldcs((const float4*)(p + 2 * NPIX));

        float gy0 = 0.299f * r4.x + 0.587f * g4.x + 0.114f * b4.x;
        float gy1 = 0.299f * r4.y + 0.587f * g4.y + 0.114f * b4.y;
        float gy2 = 0.299f * r4.z + 0.587f * g4.z + 0.114f * b4.z;
        float gy3 = 0.299f * r4.w + 0.587f * g4.w + 0.114f * b4.w;

        acc.x += (r4.x + g4.x + b4.x) * (1.0f / 3.0f);
        acc.y += (r4.y + g4.y + b4.y) * (1.0f / 3.0f);
        acc.z += (r4.z + g4.z + b4.z) * (1.0f / 3.0f);
        acc.w += (r4.w + g4.w + b4.w) * (1.0f / 3.0f);
        dirty = true;

        float gnext = __shfl_down_sync(mask, gy0, 1);
        if (lane == 31 && col + 4 < W) {
            const float* q = p + 4;
            gnext = 0.299f * q[0] + 0.587f * q[NPIX] + 0.114f * q[2 * NPIX];
        }

        int i0 = min(max((int)(gy0 * 255.0f), 0), 255);
        int i1 = min(max((int)(gy1 * 255.0f), 0), 255);
        int i2 = min(max((int)(gy2 * 255.0f), 0), 255);
        int i3 = min(max((int)(gy3 * 255.0f), 0), 255);

        int d;
        d = i0 - i1; d2 += (unsigned)(d * d);
        d = i1 - i2; d2 += (unsigned)(d * d);
        d = i2 - i3; d2 += (unsigned)(d * d);
        if (col + 3 < W - 1) {
            int i4 = min(max((int)(gnext * 255.0f), 0), 255);
            d = i3 - i4; d2 += (unsigned)(d * d);
        }

        if (r + 1 == next) {
            float* dst = abandb + (size_t)ab * W;
            atomicAdd(dst + 0, acc.x);
            atomicAdd(dst + 1, acc.y);
            atomicAdd(dst + 2, acc.z);
            atomicAdd(dst + 3, acc.w);
            acc = make_float4(0.f, 0.f, 0.f, 0.f);
            dirty = false;
            ab++;
            next = c_bs[ab + 1];
        }
    }
    if (dirty) {
        float* dst = abandb + (size_t)ab * W;
        atomicAdd(dst + 0, acc.x);
        atomicAdd(dst + 1, acc.y);
        atomicAdd(dst + 2, acc.z);
        atomicAdd(dst + 3, acc.w);
    }

    d2 = __reduce_add_sync(mask, d2);
    if (lane == 0) s_w[t >> 5] = d2;
    __syncthreads();
    if (t == 0) {
        unsigned tot = 0;
#pragma unroll
        for (int i = 0; i < 8; i++) tot += s_w[i];
        g_d2part[blockIdx.x] = tot;
    }
}

// ---------------- K2: segment means (tier computed inline) ----------------
__global__ __launch_bounds__(32) void k_segmean(float* __restrict__ out, int write_tail) {
    int b = blockIdx.z, m = blockIdx.y, seg = blockIdx.x;
    int lane = threadIdx.x;
    unsigned mask = 0xFFFFFFFFu;

    // inline complexity reduce (64 u32 partials, L2-hot) -> tier, all lanes
    unsigned long long s64 = (unsigned long long)g_d2part[b * 64 + lane]
                           + (unsigned long long)g_d2part[b * 64 + 32 + lane];
#pragma unroll
    for (int o = 16; o > 0; o >>= 1) s64 += __shfl_xor_sync(mask, s64, o);
    float comp = (float)s64 / (float)NPAIRS;
    int tier = (comp < 50.0f) ? 0 : ((comp < 150.0f) ? 1 : 2);

    if (m == 0 && seg == 0 && lane == 0) {
        g_tier[b] = tier;
        if (write_tail) {
            out[SAL_ELEMS + b] = comp;
#pragma unroll
            for (int mm = 0; mm < 3; mm++)
                out[SAL_ELEMS + B + b * 3 + mm] = (float)(c_base[tier] + (mm - 1) * c_incr[tier]);
        }
    }

    int gr = c_gr[tier][m], gc = c_gc[tier][m];
    if (seg >= gr * gc) return;
    int r = seg / gc, c = seg - r * gc;
    int r0 = (r * H + gr - 1) / gr;
    int r1 = ((r + 1) * H + gr - 1) / gr; if (r1 > H) r1 = H;
    int c0 = (c * W + gc - 1) / gc;
    int c1 = ((c + 1) * W + gc - 1) / gc; if (c1 > W) c1 = W;

    float s = 0.0f;
    for (int ab = 0; ab < NAB; ab++) {
        int bs = c_bs[ab];
        if (bs >= r0 && bs < r1) {
            const float* p = g_aband + ((size_t)b * MAXAB + ab) * W;
            for (int col = c0 + lane; col < c1; col += 32) s += p[col];
        }
    }
#pragma unroll
    for (int o = 16; o > 0; o >>= 1) s += __shfl_down_sync(mask, s, o);
    if (lane == 0) {
        int cnt = (r1 - r0) * (c1 - c0);
        g_segmean[((size_t)b * 3 + m) * 256 + seg] = s / (float)cnt;
    }
}

// ---------------- K3: fill saliency, 8 floats/thread, branch-free ----------------
// Column bands are >= 73 px wide, so 8 consecutive pixels cross at most one
// boundary: two loads + per-element select, no divergence.
__global__ __launch_bounds__(256) void k_fill(float* __restrict__ out) {
    int idx = blockIdx.x * 256 + threadIdx.x;   // 8-float group index
    int bm = idx >> 17;                          // 131072 groups per map
    int within = idx & 131071;
    int row = within >> 7;                       // 128 groups per row
    int col = (within & 127) << 3;

    int b = bm / 3;
    int m = bm - b * 3;
    int tier = g_tier[b];
    int gr = c_gr[tier][m], gc = c_gc[tier][m];
    const float* sm = g_segmean + (size_t)bm * 256;

    int rb = (row * gr) >> 10;
    int basei = rb * gc;

    int cb0 = (col * gc) >> 10;
    int cb7 = ((col + 7) * gc) >> 10;
    float a = sm[basei + cb0];
    float bv = sm[basei + cb7];
    int bpos = (cb7 * 1024 + gc - 1) / gc;      // first column in band cb7

    float4 q0, q1;
    q0.x = (col + 0 >= bpos) ? bv : a;
    q0.y = (col + 1 >= bpos) ? bv : a;
    q0.z = (col + 2 >= bpos) ? bv : a;
    q0.w = (col + 3 >= bpos) ? bv : a;
    q1.x = (col + 4 >= bpos) ? bv : a;
    q1.y = (col + 5 >= bpos) ? bv : a;
    q1.z = (col + 6 >= bpos) ? bv : a;
    q1.w = (col + 7 >= bpos) ? bv : a;

    float4* dst = (float4*)(out + (size_t)bm * NPIX + (size_t)row * W + col);
    __stcs(dst + 0, q0);
    __stcs(dst + 1, q1);
}

// ---------------- launch ----------------
extern "C" void kernel_launch(void* const* d_in, const int* in_sizes, int n_in,
                              void* d_out, int out_size) {
    const float* img = (const float*)d_in[0];
    float* out = (float*)d_out;
    int write_tail = (out_size >= SAL_ELEMS + B + B * 3) ? 1 : 0;

    k_zero<<<512, 256>>>();
    k_gray<<<B * 64, 256>>>(img);
    dim3 gsm(182, 3, B);
    k_segmean<<<gsm, 32>>>(out, write_tail);
    k_fill<<<(SAL_ELEMS / 8) / 256, 256>>>(out);
}

// round 13
// speedup vs baseline: 1.6561x; 1.1040x over previous
#include <cuda_runtime.h>
#include <stdint.h>

#define B 8
#define H 1024
#define W 1024
#define NPIX (H * W)
#define SAL_ELEMS (B * 3 * NPIX)
#define NPAIRS (H * (W - 1))
#define MAXAB 64      // g_aband stride (>= NAB)
#define NAB 52        // merged band count

// ---------------- scratch ----------------
__device__ float g_aband[B * MAXAB * W];      // [b][atomic band][col], 2 MB
__device__ unsigned g_d2part[B * 64];
__device__ int g_tier[B];
__device__ float g_segmean[B * 3 * 256];

// tier x map geometry: n = BASE[t]+(m-1)*INCR[t]; gr=round(sqrt n); gc=ceil(n/gr)
__constant__ int c_gr[3][3] = { {4, 5, 6}, {8, 9, 10}, {11, 12, 13} };
__constant__ int c_gc[3][3] = { {5, 6, 7}, {9, 9, 10}, {12, 13, 14} };
__constant__ int c_base[3] = { 30, 80, 150 };
__constant__ int c_incr[3] = { 10, 15, 25 };

// Merged row-band boundaries: union over gr in {4,5,6,8,9,10,11,12,13} of
// { ceil(1024*k/gr) : k=0..gr-1 }, sorted, + sentinel 1024. 52 bands.
__constant__ int c_bs[NAB + 1] = {
    0, 79, 86, 94, 103, 114, 128, 158, 171, 187, 205, 228, 237, 256, 280,
    308, 316, 342, 373, 384, 394, 410, 427, 456, 466, 473, 512, 552, 559,
    569, 598, 615, 631, 640, 652, 683, 709, 717, 745, 768, 788, 797, 820,
    838, 854, 867, 896, 911, 922, 931, 939, 946, 1024
};

// ---------------- K0: zero atomic-band accumulators ----------------
__global__ __launch_bounds__(256) void k_zero() {
    int i = blockIdx.x * 256 + threadIdx.x;     // float4 index; 512*256 exact
    ((float4*)g_aband)[i] = make_float4(0.f, 0.f, 0.f, 0.f);
}

// ---------------- K1: fused gray + complexity + row-band sums ----------------
// Block = (b, 16-row chunk): 512 balanced blocks. Per-thread accumulator
// flushes to g_aband via atomicAdd only at merged band boundaries.
__global__ __launch_bounds__(256) void k_gray(const float* __restrict__ img) {
    __shared__ unsigned s_w[8];

    int chunk = blockIdx.x & 63;
    int b = blockIdx.x >> 6;
    int rc0 = chunk << 4;
    int t = threadIdx.x;
    int col = t << 2;
    int lane = t & 31;
    unsigned mask = 0xFFFFFFFFu;

    // locate atomic band containing rc0 (uniform walk over constant table)
    int ab = 0;
    while (c_bs[ab + 1] <= rc0) ab++;
    int next = c_bs[ab + 1];

    float4 acc = make_float4(0.f, 0.f, 0.f, 0.f);
    bool dirty = false;
    unsigned d2 = 0;
    float* abandb = g_aband + (size_t)b * MAXAB * W + col;
    const float* base = img + (size_t)b * 3 * NPIX + col;

#pragma unroll 4
    for (int rr = 0; rr < 16; rr++) {
        int r = rc0 + rr;
        const float* p = base + (size_t)r * W;
        float4 r4 = __ldcs((const float4*)p);
        float4 g4 = __ldcs((const float4*)(p + NPIX));
        float4 b4 = __ldcs((const float4*)(p + 2 * NPIX));

        float gy0 = 0.299f * r4.x + 0.587f * g4.x + 0.114f * b4.x;
        float gy1 = 0.299f * r4.y + 0.587f * g4.y + 0.114f * b4.y;
        float gy2 = 0.299f * r4.z + 0.587f * g4.z + 0.114f * b4.z;
        float gy3 = 0.299f * r4.w + 0.587f * g4.w + 0.114f * b4.w;

        acc.x += (r4.x + g4.x + b4.x) * (1.0f / 3.0f);
        acc.y += (r4.y + g4.y + b4.y) * (1.0f / 3.0f);
        acc.z += (r4.z + g4.z + b4.z) * (1.0f / 3.0f);
        acc.w += (r4.w + g4.w + b4.w) * (1.0f / 3.0f);
        dirty = true;

        float gnext = __shfl_down_sync(mask, gy0, 1);
        if (lane == 31 && col + 4 < W) {
            const float* q = p + 4;
            gnext = 0.299f * q[0] + 0.587f * q[NPIX] + 0.114f * q[2 * NPIX];
        }

        int i0 = min(max((int)(gy0 * 255.0f), 0), 255);
        int i1 = min(max((int)(gy1 * 255.0f), 0), 255);
        int i2 = min(max((int)(gy2 * 255.0f), 0), 255);
        int i3 = min(max((int)(gy3 * 255.0f), 0), 255);

        int d;
        d = i0 - i1; d2 += (unsigned)(d * d);
        d = i1 - i2; d2 += (unsigned)(d * d);
        d = i2 - i3; d2 += (unsigned)(d * d);
        if (col + 3 < W - 1) {
            int i4 = min(max((int)(gnext * 255.0f), 0), 255);
            d = i3 - i4; d2 += (unsigned)(d * d);
        }

        if (r + 1 == next) {
            float* dst = abandb + (size_t)ab * W;
            atomicAdd(dst + 0, acc.x);
            atomicAdd(dst + 1, acc.y);
            atomicAdd(dst + 2, acc.z);
            atomicAdd(dst + 3, acc.w);
            acc = make_float4(0.f, 0.f, 0.f, 0.f);
            dirty = false;
            ab++;
            next = c_bs[ab + 1];
        }
    }
    if (dirty) {
        float* dst = abandb + (size_t)ab * W;
        atomicAdd(dst + 0, acc.x);
        atomicAdd(dst + 1, acc.y);
        atomicAdd(dst + 2, acc.z);
        atomicAdd(dst + 3, acc.w);
    }

    d2 = __reduce_add_sync(mask, d2);
    if (lane == 0) s_w[t >> 5] = d2;
    __syncthreads();
    if (t == 0) {
        unsigned tot = 0;
#pragma unroll
        for (int i = 0; i < 8; i++) tot += s_w[i];
        g_d2part[blockIdx.x] = tot;
    }
}

// ---------------- K2: segment means (tier computed inline) ----------------
__global__ __launch_bounds__(32) void k_segmean(float* __restrict__ out, int write_tail) {
    int b = blockIdx.z, m = blockIdx.y, seg = blockIdx.x;
    int lane = threadIdx.x;
    unsigned mask = 0xFFFFFFFFu;

    // inline complexity reduce (64 u32 partials, L2-hot) -> tier, all lanes
    unsigned long long s64 = (unsigned long long)g_d2part[b * 64 + lane]
                           + (unsigned long long)g_d2part[b * 64 + 32 + lane];
#pragma unroll
    for (int o = 16; o > 0; o >>= 1) s64 += __shfl_xor_sync(mask, s64, o);
    float comp = (float)s64 / (float)NPAIRS;
    int tier = (comp < 50.0f) ? 0 : ((comp < 150.0f) ? 1 : 2);

    if (m == 0 && seg == 0 && lane == 0) {
        g_tier[b] = tier;
        if (write_tail) {
            out[SAL_ELEMS + b] = comp;
#pragma unroll
            for (int mm = 0; mm < 3; mm++)
                out[SAL_ELEMS + B + b * 3 + mm] = (float)(c_base[tier] + (mm - 1) * c_incr[tier]);
        }
    }

    int gr = c_gr[tier][m], gc = c_gc[tier][m];
    if (seg >= gr * gc) return;
    int r = seg / gc, c = seg - r * gc;
    int r0 = (r * H + gr - 1) / gr;
    int r1 = ((r + 1) * H + gr - 1) / gr; if (r1 > H) r1 = H;
    int c0 = (c * W + gc - 1) / gc;
    int c1 = ((c + 1) * W + gc - 1) / gc; if (c1 > W) c1 = W;

    float s = 0.0f;
    for (int ab = 0; ab < NAB; ab++) {
        int bs = c_bs[ab];
        if (bs >= r0 && bs < r1) {
            const float* p = g_aband + ((size_t)b * MAXAB + ab) * W;
            for (int col = c0 + lane; col < c1; col += 32) s += p[col];
        }
    }
#pragma unroll
    for (int o = 16; o > 0; o >>= 1) s += __shfl_down_sync(mask, s, o);
    if (lane == 0) {
        int cnt = (r1 - r0) * (c1 - c0);
        g_segmean[((size_t)b * 3 + m) * 256 + seg] = s / (float)cnt;
    }
}

// ---------------- K3: fill saliency, 4 floats/thread (proven-best form) ----------
__global__ __launch_bounds__(256) void k_fill(float* __restrict__ out) {
    int idx = blockIdx.x * blockDim.x + threadIdx.x;   // quad index
    int bm = idx >> 18;
    int within = idx & 262143;
    int row = within >> 8;
    int col = (within & 255) << 2;

    int b = bm / 3;
    int m = bm - b * 3;
    int tier = g_tier[b];
    int gr = c_gr[tier][m], gc = c_gc[tier][m];
    const float* sm = g_segmean + (size_t)bm * 256;

    int rb = (row * gr) >> 10;
    int basei = rb * gc;
    float4 v;
    v.x = sm[basei + (((col + 0) * gc) >> 10)];
    v.y = sm[basei + (((col + 1) * gc) >> 10)];
    v.z = sm[basei + (((col + 2) * gc) >> 10)];
    v.w = sm[basei + (((col + 3) * gc) >> 10)];
    __stcs((float4*)(out + (size_t)bm * NPIX + (size_t)row * W + col), v);
}

// ---------------- launch ----------------
extern "C" void kernel_launch(void* const* d_in, const int* in_sizes, int n_in,
                              void* d_out, int out_size) {
    const float* img = (const float*)d_in[0];
    float* out = (float*)d_out;
    int write_tail = (out_size >= SAL_ELEMS + B + B * 3) ? 1 : 0;

    k_zero<<<512, 256>>>();
    k_gray<<<B * 64, 256>>>(img);
    dim3 gsm(182, 3, B);
    k_segmean<<<gsm, 32>>>(out, write_tail);
    k_fill<<<(SAL_ELEMS / 4) / 256, 256>>>(out);
}